// round 4
// baseline (speedup 1.0000x reference)
#include <cuda_runtime.h>

#define BATCH 48
#define HH 128
#define WW 128
#define HW 16384

// ---------------- scratch (device globals; no allocation) ----------------
__device__ float g_in0[BATCH * 16 * HW];   // conv1x1(high) output
__device__ float g_v[BATCH * 16 * HW];     // branch conv output (pre-GN "high")
__device__ float g_u[BATCH * 16 * HW];     // conv1x1(low) output (pre-GN "low")
__device__ float g_z[BATCH * 16 * HW];     // ref conv output (pre-GN)
__device__ float g_seg[BATCH * HW];        // seg logits at 128x128
__device__ float g_part_high[BATCH * 32 * 2];
__device__ float g_part_low[BATCH * 16 * 4];
__device__ float g_part_z[BATCH * 32 * 4];
__device__ float g_stats1[BATCH * 6];      // mH, rH, mL0, rL0, mL1, rL1
__device__ float g_stats2[BATCH * 4];      // m0, r0, m1, r1

typedef unsigned long long u64;

__device__ __forceinline__ u64 fma2(u64 a, u64 b, u64 c) {
    u64 d;
    asm("fma.rn.f32x2 %0, %1, %2, %3;" : "=l"(d) : "l"(a), "l"(b), "l"(c));
    return d;
}
__device__ __forceinline__ u64 pk2(float lo, float hi) {
    u64 r;
    asm("mov.b64 %0, {%1, %2};" : "=l"(r) : "f"(lo), "f"(hi));
    return r;
}
__device__ __forceinline__ void upk2(u64 v, float& lo, float& hi) {
    asm("mov.b64 {%0, %1}, %2;" : "=f"(lo), "=f"(hi) : "l"(v));
}

__device__ __forceinline__ float mish_f(float x) {
    // x * tanh(softplus(x)) = x * (e^2+2e)/(e^2+2e+2), e = exp(x)
    if (x > 20.f) return x;
    float e = __expf(x);
    float n = e * (e + 2.f);
    return x * n / (n + 2.f);
}

// ---------------- K1: in0 = conv1x1(high, Wc0)  (32 -> 16) ----------------
__global__ __launch_bounds__(256) void k1_conv1x1_high(
    const float* __restrict__ high, const float* __restrict__ Wc0) {
    __shared__ float sw[512];
    int t = threadIdx.x;
    for (int i = t; i < 512; i += 256) sw[i] = Wc0[i];
    __syncthreads();
    int b = blockIdx.y;
    int p0 = blockIdx.x * 1024;
    const float* hb = high + (size_t)b * 32 * HW + p0 + t;
    float* ob = g_in0 + (size_t)b * 16 * HW + p0 + t;
    float acc[4][16];
#pragma unroll
    for (int i = 0; i < 4; i++)
#pragma unroll
        for (int o = 0; o < 16; o++) acc[i][o] = 0.f;
    for (int c = 0; c < 32; c++) {
        float x0 = hb[c * HW], x1 = hb[c * HW + 256];
        float x2 = hb[c * HW + 512], x3 = hb[c * HW + 768];
#pragma unroll
        for (int o = 0; o < 16; o++) {
            float w = sw[o * 32 + c];
            acc[0][o] += x0 * w; acc[1][o] += x1 * w;
            acc[2][o] += x2 * w; acc[3][o] += x3 * w;
        }
    }
#pragma unroll
    for (int o = 0; o < 16; o++) {
        ob[o * HW] = acc[0][o]; ob[o * HW + 256] = acc[1][o];
        ob[o * HW + 512] = acc[2][o]; ob[o * HW + 768] = acc[3][o];
    }
}

// ---------------- K2: v = [conv3x3(in0[0:8],Wc1,d1) ; conv3x3(in0[8:16],Wc2,d2)]
// tile 32x16, 128 threads. Each thread: x-pair (2 px) x 2 rows, f32x2 packed math.
__global__ __launch_bounds__(128) void k2_branch(
    const float* __restrict__ Wc1, const float* __restrict__ Wc2) {
    __shared__ float sx[5760];   // phase1: [8][18][34], phase2: [8][20][36]
    __shared__ u64 sw2a[576];    // Wc1 duplicated pairs
    __shared__ u64 sw2b[576];    // Wc2 duplicated pairs
    __shared__ float red[128];
    const u64* sx64 = (const u64*)sx;
    int t = threadIdx.x;
    int b = blockIdx.y;
    int tile = blockIdx.x;
    int x0 = (tile & 3) * 32, y0 = (tile >> 2) * 16;
    for (int i = t; i < 576; i += 128) {
        float w1 = Wc1[i], w2v = Wc2[i];
        sw2a[i] = pk2(w1, w1);
        sw2b[i] = pk2(w2v, w2v);
    }
    int lx2 = t & 15;            // x-pair index: pixels 2*lx2, 2*lx2+1
    int ry = t >> 4;             // 0..7, rows ry*2, ry*2+1
    const float* in0b = g_in0 + (size_t)b * 16 * HW;
    float* vb = g_v + (size_t)b * 16 * HW;
    float ls1 = 0.f, ls2 = 0.f;

    // ---- phase 1: channels 0..7, dilation 1, halo 1 (18 x 34) ----
    for (int i = t; i < 8 * 18 * 34; i += 128) {
        int c = i / 612; int rem = i - c * 612;
        int yy = rem / 34; int xx = rem - yy * 34;
        int gy = y0 - 1 + yy, gx = x0 - 1 + xx;
        float val = 0.f;
        if ((unsigned)gy < 128u && (unsigned)gx < 128u)
            val = in0b[c * HW + gy * WW + gx];
        sx[i] = val;
    }
    __syncthreads();
    {
        u64 acc0[8], acc1[8];
        u64 zero = 0ull;
#pragma unroll
        for (int o = 0; o < 8; o++) { acc0[o] = zero; acc1[o] = zero; }
        for (int ci = 0; ci < 8; ci++) {
            int cb = ci * 306;   // u64 units per channel (612/2)
#pragma unroll
            for (int ky = 0; ky < 3; ky++) {
                int rr = ry * 2 + ky;
                u64 a0 = sx64[cb + rr * 17 + lx2];
                u64 a1 = sx64[cb + rr * 17 + lx2 + 1];
                u64 b0 = sx64[cb + (rr + 1) * 17 + lx2];
                u64 b1 = sx64[cb + (rr + 1) * 17 + lx2 + 1];
                float a0l, a0h, a1l, a1h, b0l, b0h, b1l, b1h;
                upk2(a0, a0l, a0h); upk2(a1, a1l, a1h);
                upk2(b0, b0l, b0h); upk2(b1, b1l, b1h);
                u64 pa[3], pb[3];
                pa[0] = a0; pa[1] = pk2(a0h, a1l); pa[2] = a1;
                pb[0] = b0; pb[1] = pk2(b0h, b1l); pb[2] = b1;
#pragma unroll
                for (int kx = 0; kx < 3; kx++) {
#pragma unroll
                    for (int o = 0; o < 8; o++) {
                        u64 w = sw2a[o * 72 + ci * 9 + ky * 3 + kx];
                        acc0[o] = fma2(pa[kx], w, acc0[o]);
                        acc1[o] = fma2(pb[kx], w, acc1[o]);
                    }
                }
            }
        }
#pragma unroll
        for (int r = 0; r < 2; r++) {
            int gy = y0 + ry * 2 + r;
#pragma unroll
            for (int o = 0; o < 8; o++) {
                float z0, z1;
                upk2(r == 0 ? acc0[o] : acc1[o], z0, z1);
                float2 st; st.x = z0; st.y = z1;
                *(float2*)&vb[o * HW + gy * WW + x0 + 2 * lx2] = st;
                ls1 += z0 + z1; ls2 += z0 * z0 + z1 * z1;
            }
        }
    }
    __syncthreads();
    // ---- phase 2: channels 8..15, dilation 2, halo 2 (20 x 36) ----
    for (int i = t; i < 8 * 20 * 36; i += 128) {
        int c = i / 720; int rem = i - c * 720;
        int yy = rem / 36; int xx = rem - yy * 36;
        int gy = y0 - 2 + yy, gx = x0 - 2 + xx;
        float val = 0.f;
        if ((unsigned)gy < 128u && (unsigned)gx < 128u)
            val = in0b[(c + 8) * HW + gy * WW + gx];
        sx[i] = val;
    }
    __syncthreads();
    {
        u64 acc0[8], acc1[8];
        u64 zero = 0ull;
#pragma unroll
        for (int o = 0; o < 8; o++) { acc0[o] = zero; acc1[o] = zero; }
        for (int ci = 0; ci < 8; ci++) {
            int cb = ci * 360;   // u64 units per channel (720/2)
#pragma unroll
            for (int ky = 0; ky < 3; ky++) {
                int rr = ry * 2 + 2 * ky;
                // dilation 2: taps at +0,+2,+4 floats = +0,+1,+2 u64 -> all aligned
                u64 pa[3], pb[3];
#pragma unroll
                for (int kx = 0; kx < 3; kx++) {
                    pa[kx] = sx64[cb + rr * 18 + lx2 + kx];
                    pb[kx] = sx64[cb + (rr + 1) * 18 + lx2 + kx];
                }
#pragma unroll
                for (int kx = 0; kx < 3; kx++) {
#pragma unroll
                    for (int o = 0; o < 8; o++) {
                        u64 w = sw2b[o * 72 + ci * 9 + ky * 3 + kx];
                        acc0[o] = fma2(pa[kx], w, acc0[o]);
                        acc1[o] = fma2(pb[kx], w, acc1[o]);
                    }
                }
            }
        }
#pragma unroll
        for (int r = 0; r < 2; r++) {
            int gy = y0 + ry * 2 + r;
#pragma unroll
            for (int o = 0; o < 8; o++) {
                float z0, z1;
                upk2(r == 0 ? acc0[o] : acc1[o], z0, z1);
                float2 st; st.x = z0; st.y = z1;
                *(float2*)&vb[(o + 8) * HW + gy * WW + x0 + 2 * lx2] = st;
                ls1 += z0 + z1; ls2 += z0 * z0 + z1 * z1;
            }
        }
    }
    // ---- deterministic block reduce of (ls1, ls2) ----
    red[t] = ls1; __syncthreads();
    for (int s = 64; s > 0; s >>= 1) { if (t < s) red[t] += red[t + s]; __syncthreads(); }
    if (t == 0) g_part_high[(b * 32 + tile) * 2 + 0] = red[0];
    __syncthreads();
    red[t] = ls2; __syncthreads();
    for (int s = 64; s > 0; s >>= 1) { if (t < s) red[t] += red[t + s]; __syncthreads(); }
    if (t == 0) g_part_high[(b * 32 + tile) * 2 + 1] = red[0];
}

// ---------------- K3: u = conv1x1(low, Wlow) (24 -> 16), + GN-low partials
__global__ __launch_bounds__(256) void k3_low(
    const float* __restrict__ low, const float* __restrict__ Wlow) {
    __shared__ float sw[384];
    __shared__ float red[256];
    int t = threadIdx.x;
    int b = blockIdx.y;
    int p0 = blockIdx.x * 1024;
    for (int i = t; i < 384; i += 256) sw[i] = Wlow[i];
    __syncthreads();
    const float* lb = low + (size_t)b * 24 * HW + p0 + t;
    float* ub = g_u + (size_t)b * 16 * HW + p0 + t;
    float acc[4][16];
#pragma unroll
    for (int i = 0; i < 4; i++)
#pragma unroll
        for (int o = 0; o < 16; o++) acc[i][o] = 0.f;
    for (int c = 0; c < 24; c++) {
        float x0 = lb[c * HW], x1 = lb[c * HW + 256];
        float x2 = lb[c * HW + 512], x3 = lb[c * HW + 768];
#pragma unroll
        for (int o = 0; o < 16; o++) {
            float w = sw[o * 24 + c];
            acc[0][o] += x0 * w; acc[1][o] += x1 * w;
            acc[2][o] += x2 * w; acc[3][o] += x3 * w;
        }
    }
    float sv[4] = {0.f, 0.f, 0.f, 0.f};   // s0,q0,s1,q1
#pragma unroll
    for (int o = 0; o < 16; o++) {
        float v0 = acc[0][o], v1 = acc[1][o], v2 = acc[2][o], v3 = acc[3][o];
        ub[o * HW] = v0; ub[o * HW + 256] = v1;
        ub[o * HW + 512] = v2; ub[o * HW + 768] = v3;
        int g = (o >> 3) * 2;
        sv[g] += v0 + v1 + v2 + v3;
        sv[g + 1] += v0 * v0 + v1 * v1 + v2 * v2 + v3 * v3;
    }
#pragma unroll
    for (int j = 0; j < 4; j++) {
        red[t] = sv[j]; __syncthreads();
        for (int s = 128; s > 0; s >>= 1) { if (t < s) red[t] += red[t + s]; __syncthreads(); }
        if (t == 0) g_part_low[(b * 16 + blockIdx.x) * 4 + j] = red[0];
        __syncthreads();
    }
}

// ---------------- K4: finalize stats for GN-high (1 group) and GN-low (2 groups)
__global__ void k4_stats1() {
    int b = blockIdx.x; int t = threadIdx.x; // 32 threads
    float h1 = g_part_high[(b * 32 + t) * 2 + 0];
    float h2 = g_part_high[(b * 32 + t) * 2 + 1];
    for (int o = 16; o; o >>= 1) {
        h1 += __shfl_xor_sync(0xffffffffu, h1, o);
        h2 += __shfl_xor_sync(0xffffffffu, h2, o);
    }
    float l[4];
#pragma unroll
    for (int j = 0; j < 4; j++) {
        float v = (t < 16) ? g_part_low[(b * 16 + t) * 4 + j] : 0.f;
        for (int o = 16; o; o >>= 1) v += __shfl_xor_sync(0xffffffffu, v, o);
        l[j] = v;
    }
    if (t == 0) {
        float nH = 16.f * HW;
        float mH = h1 / nH;
        g_stats1[b * 6 + 0] = mH;
        g_stats1[b * 6 + 1] = rsqrtf(h2 / nH - mH * mH + 1e-5f);
        float nL = 8.f * HW;
        float m0 = l[0] / nL;
        g_stats1[b * 6 + 2] = m0;
        g_stats1[b * 6 + 3] = rsqrtf(l[1] / nL - m0 * m0 + 1e-5f);
        float m1 = l[2] / nL;
        g_stats1[b * 6 + 4] = m1;
        g_stats1[b * 6 + 5] = rsqrtf(l[3] / nL - m1 * m1 + 1e-5f);
    }
}

// ---------------- K5: r = mish(GN(v)+GN(u)); z = conv3x3(r, Wref); + GN-z partials
// tile 32x16, 128 threads. Each thread: x-pair x 2 rows, f32x2 packed math.
__global__ __launch_bounds__(128) void k5_ref(
    const float* __restrict__ Wref,
    const float* __restrict__ gbn, const float* __restrict__ bbn,
    const float* __restrict__ glow, const float* __restrict__ blow) {
    __shared__ float sr[9792];    // [16][18][34]
    __shared__ u64 sw2[2304];     // [16][16][9] duplicated pairs
    __shared__ float sa1[16], sa2[16], sa3[16];
    __shared__ float red[128];
    const u64* sr64 = (const u64*)sr;
    int t = threadIdx.x;
    int b = blockIdx.y;
    int tile = blockIdx.x;
    int x0 = (tile & 3) * 32, y0 = (tile >> 2) * 16;
    for (int i = t; i < 2304; i += 128) {
        float w = Wref[i];
        sw2[i] = pk2(w, w);
    }
    if (t < 16) {
        int c = t, g = c >> 3;
        float mH = g_stats1[b * 6 + 0], rH = g_stats1[b * 6 + 1];
        float mL = g_stats1[b * 6 + 2 + 2 * g], rL = g_stats1[b * 6 + 3 + 2 * g];
        float a1 = rH * gbn[c], a2 = rL * glow[c];
        sa1[c] = a1; sa2[c] = a2;
        sa3[c] = bbn[c] + blow[c] - mH * a1 - mL * a2;
    }
    __syncthreads();
    const float* vb = g_v + (size_t)b * 16 * HW;
    const float* ub = g_u + (size_t)b * 16 * HW;
    for (int i = t; i < 9792; i += 128) {
        int c = i / 612; int rem = i - c * 612;
        int yy = rem / 34; int xx = rem - yy * 34;
        int gy = y0 - 1 + yy, gx = x0 - 1 + xx;
        float val = 0.f;
        if ((unsigned)gy < 128u && (unsigned)gx < 128u) {
            int off = c * HW + gy * WW + gx;
            val = mish_f(vb[off] * sa1[c] + ub[off] * sa2[c] + sa3[c]);
        }
        sr[i] = val;
    }
    __syncthreads();
    int lx2 = t & 15;
    int ry = t >> 4;
    u64 acc0[16], acc1[16];
#pragma unroll
    for (int o = 0; o < 16; o++) { acc0[o] = 0ull; acc1[o] = 0ull; }
    for (int ci = 0; ci < 16; ci++) {
        int cb = ci * 306;   // u64 units per channel (612/2)
#pragma unroll
        for (int ky = 0; ky < 3; ky++) {
            int rr = ry * 2 + ky;
            u64 a0 = sr64[cb + rr * 17 + lx2];
            u64 a1 = sr64[cb + rr * 17 + lx2 + 1];
            u64 b0 = sr64[cb + (rr + 1) * 17 + lx2];
            u64 b1 = sr64[cb + (rr + 1) * 17 + lx2 + 1];
            float a0l, a0h, a1l, a1h, b0l, b0h, b1l, b1h;
            upk2(a0, a0l, a0h); upk2(a1, a1l, a1h);
            upk2(b0, b0l, b0h); upk2(b1, b1l, b1h);
            u64 pa[3], pb[3];
            pa[0] = a0; pa[1] = pk2(a0h, a1l); pa[2] = a1;
            pb[0] = b0; pb[1] = pk2(b0h, b1l); pb[2] = b1;
#pragma unroll
            for (int kx = 0; kx < 3; kx++) {
#pragma unroll
                for (int o = 0; o < 16; o++) {
                    u64 w = sw2[o * 144 + ci * 9 + ky * 3 + kx];
                    acc0[o] = fma2(pa[kx], w, acc0[o]);
                    acc1[o] = fma2(pb[kx], w, acc1[o]);
                }
            }
        }
    }
    float* zb = g_z + (size_t)b * 16 * HW;
    float sv[4] = {0.f, 0.f, 0.f, 0.f};
#pragma unroll
    for (int r = 0; r < 2; r++) {
        int gy = y0 + ry * 2 + r;
#pragma unroll
        for (int o = 0; o < 16; o++) {
            float z0, z1;
            upk2(r == 0 ? acc0[o] : acc1[o], z0, z1);
            float2 st; st.x = z0; st.y = z1;
            *(float2*)&zb[o * HW + gy * WW + x0 + 2 * lx2] = st;
            int g = (o >> 3) * 2;
            sv[g] += z0 + z1; sv[g + 1] += z0 * z0 + z1 * z1;
        }
    }
#pragma unroll
    for (int j = 0; j < 4; j++) {
        red[t] = sv[j]; __syncthreads();
        for (int s = 64; s > 0; s >>= 1) { if (t < s) red[t] += red[t + s]; __syncthreads(); }
        if (t == 0) g_part_z[(b * 32 + tile) * 4 + j] = red[0];
        __syncthreads();
    }
}

// ---------------- K6: finalize GN-z stats (2 groups)
__global__ void k6_stats2() {
    int b = blockIdx.x; int t = threadIdx.x; // 32 threads
    float l[4];
#pragma unroll
    for (int j = 0; j < 4; j++) {
        float v = g_part_z[(b * 32 + t) * 4 + j];
        for (int o = 16; o; o >>= 1) v += __shfl_xor_sync(0xffffffffu, v, o);
        l[j] = v;
    }
    if (t == 0) {
        float n = 8.f * HW;
        float m0 = l[0] / n;
        g_stats2[b * 4 + 0] = m0;
        g_stats2[b * 4 + 1] = rsqrtf(l[1] / n - m0 * m0 + 1e-5f);
        float m1 = l[2] / n;
        g_stats2[b * 4 + 2] = m1;
        g_stats2[b * 4 + 3] = rsqrtf(l[3] / n - m1 * m1 + 1e-5f);
    }
}

// ---------------- K7: seg = conv1x1(mish(GN(z)), Wseg)
__global__ __launch_bounds__(256) void k7_seg(
    const float* __restrict__ gref, const float* __restrict__ bref,
    const float* __restrict__ Wseg) {
    __shared__ float sa[16], sb[16], sws[16];
    int t = threadIdx.x, b = blockIdx.y;
    int p = blockIdx.x * 256 + t;
    if (t < 16) {
        int g = t >> 3;
        float m = g_stats2[b * 4 + 2 * g], r = g_stats2[b * 4 + 1 + 2 * g];
        float a = r * gref[t];
        sa[t] = a; sb[t] = bref[t] - m * a; sws[t] = Wseg[t];
    }
    __syncthreads();
    const float* zb = g_z + (size_t)b * 16 * HW + p;
    float acc = 0.f;
#pragma unroll
    for (int c = 0; c < 16; c++) {
        float zn = zb[c * HW] * sa[c] + sb[c];
        acc += mish_f(zn) * sws[c];
    }
    g_seg[b * HW + p] = acc;
}

// ---------------- K8: bilinear 128->512 (half-pixel centers, clamp) + sigmoid
// 4 consecutive output pixels per thread -> STG.128
__global__ __launch_bounds__(256) void k8_up(float4* __restrict__ out) {
    int idx4 = blockIdx.x * 256 + threadIdx.x;      // 48*512*512/4 = 3145728
    int idx = idx4 * 4;
    int b = idx >> 18;
    int rem = idx & 262143;
    int oy = rem >> 9, ox0 = rem & 511;
    float sy = (oy + 0.5f) * 0.25f - 0.5f;
    sy = fminf(fmaxf(sy, 0.f), 127.f);
    int y0 = (int)sy;
    float fy = sy - y0;
    int y1 = min(y0 + 1, 127);
    const float* s = g_seg + b * HW;
    const float* r0 = s + y0 * 128;
    const float* r1 = s + y1 * 128;
    float4 o4;
    float res[4];
#pragma unroll
    for (int j = 0; j < 4; j++) {
        int ox = ox0 + j;
        float sx = (ox + 0.5f) * 0.25f - 0.5f;
        sx = fminf(fmaxf(sx, 0.f), 127.f);
        int x0 = (int)sx;
        float fx = sx - x0;
        int x1 = min(x0 + 1, 127);
        float top = r0[x0] + (r0[x1] - r0[x0]) * fx;
        float bot = r1[x0] + (r1[x1] - r1[x0]) * fx;
        float v = top + (bot - top) * fy;
        res[j] = 1.f / (1.f + __expf(-v));
    }
    o4.x = res[0]; o4.y = res[1]; o4.z = res[2]; o4.w = res[3];
    out[idx4] = o4;
}

// ---------------- launch ----------------
extern "C" void kernel_launch(void* const* d_in, const int* in_sizes, int n_in,
                              void* d_out, int out_size) {
    (void)in_sizes; (void)n_in; (void)out_size;
    const float* low  = (const float*)d_in[0];
    const float* high = (const float*)d_in[1];
    const float* Wc0  = (const float*)d_in[2];
    const float* Wc1  = (const float*)d_in[3];
    const float* Wc2  = (const float*)d_in[4];
    const float* gbn  = (const float*)d_in[5];
    const float* bbn  = (const float*)d_in[6];
    const float* Wlow = (const float*)d_in[7];
    const float* glow = (const float*)d_in[8];
    const float* blow = (const float*)d_in[9];
    const float* Wref = (const float*)d_in[10];
    const float* gref = (const float*)d_in[11];
    const float* bref = (const float*)d_in[12];
    const float* Wseg = (const float*)d_in[13];
    float* out = (float*)d_out;

    k1_conv1x1_high<<<dim3(16, 48), 256>>>(high, Wc0);
    k2_branch<<<dim3(32, 48), 128>>>(Wc1, Wc2);
    k3_low<<<dim3(16, 48), 256>>>(low, Wlow);
    k4_stats1<<<48, 32>>>();
    k5_ref<<<dim3(32, 48), 128>>>(Wref, gbn, bbn, glow, blow);
    k6_stats2<<<48, 32>>>();
    k7_seg<<<dim3(64, 48), 256>>>(gref, bref, Wseg);
    k8_up<<<12288, 256>>>((float4*)out);
}

// round 5
// speedup vs baseline: 1.1958x; 1.1958x over previous
#include <cuda_runtime.h>

#define BATCH 48
#define HH 128
#define WW 128
#define HW 16384

// ---------------- scratch (device globals; no allocation) ----------------
__device__ float g_in0[BATCH * 16 * HW];   // conv1x1(high) output
__device__ float g_v[BATCH * 16 * HW];     // branch conv output (pre-GN "high")
__device__ float g_u[BATCH * 16 * HW];     // conv1x1(low) output (pre-GN "low")
__device__ float g_z[BATCH * 16 * HW];     // ref conv output (pre-GN)
__device__ float g_seg[BATCH * HW];        // seg logits at 128x128
__device__ float g_part_high[BATCH * 32 * 2];
__device__ float g_part_low[BATCH * 16 * 4];
__device__ float g_part_z[BATCH * 32 * 4];
__device__ float g_stats1[BATCH * 6];      // mH, rH, mL0, rL0, mL1, rL1
__device__ float g_stats2[BATCH * 4];      // m0, r0, m1, r1

__device__ __forceinline__ float mish_f(float x) {
    if (x > 20.f) return x;
    float e = __expf(x);
    float n = e * (e + 2.f);
    return x * n / (n + 2.f);
}

// round f32 -> tf32 bit pattern (kept in f32 register)
__device__ __forceinline__ float tf32r(float x) {
    unsigned u;
    asm("cvt.rna.tf32.f32 %0, %1;" : "=r"(u) : "f"(x));
    return __uint_as_float(u);
}

// m16n8k8 tf32 mma, fp32 accumulate (row.col)
__device__ __forceinline__ void mma8(float& d0, float& d1, float& d2, float& d3,
                                     float a0, float a1, float a2, float a3,
                                     float b0, float b1) {
    asm("mma.sync.aligned.m16n8k8.row.col.f32.tf32.tf32.f32 "
        "{%0,%1,%2,%3}, {%4,%5,%6,%7}, {%8,%9}, {%0,%1,%2,%3};"
        : "+f"(d0), "+f"(d1), "+f"(d2), "+f"(d3)
        : "r"(__float_as_uint(a0)), "r"(__float_as_uint(a1)),
          "r"(__float_as_uint(a2)), "r"(__float_as_uint(a3)),
          "r"(__float_as_uint(b0)), "r"(__float_as_uint(b1)));
}

// ---------------- K1: in0 = conv1x1(high, Wc0)  (32 -> 16) ----------------
__global__ __launch_bounds__(256) void k1_conv1x1_high(
    const float* __restrict__ high, const float* __restrict__ Wc0) {
    __shared__ float sw[512];
    int t = threadIdx.x;
    for (int i = t; i < 512; i += 256) sw[i] = Wc0[i];
    __syncthreads();
    int b = blockIdx.y;
    int p0 = blockIdx.x * 1024;
    const float* hb = high + (size_t)b * 32 * HW + p0 + t;
    float* ob = g_in0 + (size_t)b * 16 * HW + p0 + t;
    float acc[4][16];
#pragma unroll
    for (int i = 0; i < 4; i++)
#pragma unroll
        for (int o = 0; o < 16; o++) acc[i][o] = 0.f;
    for (int c = 0; c < 32; c++) {
        float x0 = hb[c * HW], x1 = hb[c * HW + 256];
        float x2 = hb[c * HW + 512], x3 = hb[c * HW + 768];
#pragma unroll
        for (int o = 0; o < 16; o++) {
            float w = sw[o * 32 + c];
            acc[0][o] += x0 * w; acc[1][o] += x1 * w;
            acc[2][o] += x2 * w; acc[3][o] += x3 * w;
        }
    }
#pragma unroll
    for (int o = 0; o < 16; o++) {
        ob[o * HW] = acc[0][o]; ob[o * HW + 256] = acc[1][o];
        ob[o * HW + 512] = acc[2][o]; ob[o * HW + 768] = acc[3][o];
    }
}

// ---------------- K2: branch convs via tf32 mma (implicit GEMM) ----------
// tile 32x16 px, 128 threads (4 warps). Per branch: M=8 (upper A half = 0),
// K=72 (9 chunks), N=512 (16 n-groups of 8 px per warp over 4 rows).
__global__ __launch_bounds__(128) void k2_branch(
    const float* __restrict__ Wc1, const float* __restrict__ Wc2) {
    __shared__ float sx[5760];       // phase1: [8][18][34], phase2: [8][20][36]
    __shared__ float swt[2][8 * 73]; // weights tf32, pitch 73 (odd bank stride)
    __shared__ float wred[8];
    int t = threadIdx.x;
    int b = blockIdx.y;
    int tile = blockIdx.x;
    int x0 = (tile & 3) * 32, y0 = (tile >> 2) * 16;
    for (int i = t; i < 8 * 73; i += 128) {
        int o = i / 73, j = i - o * 73;
        float w1 = 0.f, w2 = 0.f;
        if (j < 72) { w1 = tf32r(Wc1[o * 72 + j]); w2 = tf32r(Wc2[o * 72 + j]); }
        swt[0][i] = w1; swt[1][i] = w2;
    }
    int lane = t & 31, w4 = t >> 5;
    int grp = lane >> 2, qid = lane & 3;
    const float* in0b = g_in0 + (size_t)b * 16 * HW;
    float* vb = g_v + (size_t)b * 16 * HW;
    float ls1 = 0.f, ls2 = 0.f;

    // ---- phase 1: channels 0..7, dilation 1, halo 1 (18 x 34) ----
    for (int i = t; i < 8 * 18 * 34; i += 128) {
        int c = i / 612; int rem = i - c * 612;
        int yy = rem / 34; int xx = rem - yy * 34;
        int gy = y0 - 1 + yy, gx = x0 - 1 + xx;
        float val = 0.f;
        if ((unsigned)gy < 128u && (unsigned)gx < 128u)
            val = in0b[c * HW + gy * WW + gx];
        sx[i] = tf32r(val);
    }
    __syncthreads();
    {
        float acc[16][2];
        float dz0 = 0.f, dz1 = 0.f;      // dead upper-half accumulators (stay 0)
#pragma unroll
        for (int g = 0; g < 16; g++) { acc[g][0] = 0.f; acc[g][1] = 0.f; }
        int pixB = (w4 * 4 * 34 + grp) * 4;
#pragma unroll 1
        for (int c = 0; c < 9; c++) {
            int k0 = c * 8 + qid;
            int ci0 = k0 / 9, r0 = k0 - ci0 * 9, ky0 = r0 / 3, kx0 = r0 - ky0 * 3;
            int k1 = k0 + 4;
            int ci1 = k1 / 9, r1 = k1 - ci1 * 9, ky1 = r1 / 3, kx1 = r1 - ky1 * 3;
            const float* p0 = (const float*)((const char*)sx + pixB + (ci0 * 612 + ky0 * 34 + kx0) * 4);
            const float* p1 = (const float*)((const char*)sx + pixB + (ci1 * 612 + ky1 * 34 + kx1) * 4);
            float a0 = swt[0][grp * 73 + k0];
            float a2 = swt[0][grp * 73 + k1];
#pragma unroll
            for (int g = 0; g < 16; g++) {
                int imm = (g >> 2) * 34 + (g & 3) * 8;
                mma8(acc[g][0], acc[g][1], dz0, dz1, a0, 0.f, a2, 0.f, p0[imm], p1[imm]);
            }
        }
#pragma unroll
        for (int g = 0; g < 16; g++) {
            int gy = y0 + w4 * 4 + (g >> 2);
            int gx = x0 + (g & 3) * 8 + 2 * qid;
            float d0 = acc[g][0], d1 = acc[g][1];
            float2 st; st.x = d0; st.y = d1;
            *(float2*)&vb[grp * HW + gy * WW + gx] = st;
            ls1 += d0 + d1; ls2 += d0 * d0 + d1 * d1;
        }
    }
    __syncthreads();
    // ---- phase 2: channels 8..15, dilation 2, halo 2 (20 x 36) ----
    for (int i = t; i < 8 * 20 * 36; i += 128) {
        int c = i / 720; int rem = i - c * 720;
        int yy = rem / 36; int xx = rem - yy * 36;
        int gy = y0 - 2 + yy, gx = x0 - 2 + xx;
        float val = 0.f;
        if ((unsigned)gy < 128u && (unsigned)gx < 128u)
            val = in0b[(c + 8) * HW + gy * WW + gx];
        sx[i] = tf32r(val);
    }
    __syncthreads();
    {
        float acc[16][2];
        float dz0 = 0.f, dz1 = 0.f;
#pragma unroll
        for (int g = 0; g < 16; g++) { acc[g][0] = 0.f; acc[g][1] = 0.f; }
        int pixB = (w4 * 4 * 36 + grp) * 4;
#pragma unroll 1
        for (int c = 0; c < 9; c++) {
            int k0 = c * 8 + qid;
            int ci0 = k0 / 9, r0 = k0 - ci0 * 9, ky0 = r0 / 3, kx0 = r0 - ky0 * 3;
            int k1 = k0 + 4;
            int ci1 = k1 / 9, r1 = k1 - ci1 * 9, ky1 = r1 / 3, kx1 = r1 - ky1 * 3;
            const float* p0 = (const float*)((const char*)sx + pixB + (ci0 * 720 + ky0 * 72 + kx0 * 2) * 4);
            const float* p1 = (const float*)((const char*)sx + pixB + (ci1 * 720 + ky1 * 72 + kx1 * 2) * 4);
            float a0 = swt[1][grp * 73 + k0];
            float a2 = swt[1][grp * 73 + k1];
#pragma unroll
            for (int g = 0; g < 16; g++) {
                int imm = (g >> 2) * 36 + (g & 3) * 8;
                mma8(acc[g][0], acc[g][1], dz0, dz1, a0, 0.f, a2, 0.f, p0[imm], p1[imm]);
            }
        }
#pragma unroll
        for (int g = 0; g < 16; g++) {
            int gy = y0 + w4 * 4 + (g >> 2);
            int gx = x0 + (g & 3) * 8 + 2 * qid;
            float d0 = acc[g][0], d1 = acc[g][1];
            float2 st; st.x = d0; st.y = d1;
            *(float2*)&vb[(grp + 8) * HW + gy * WW + gx] = st;
            ls1 += d0 + d1; ls2 += d0 * d0 + d1 * d1;
        }
    }
    // ---- deterministic reduce: warp shuffle + fixed-order combine ----
#pragma unroll
    for (int o = 16; o; o >>= 1) {
        ls1 += __shfl_xor_sync(0xffffffffu, ls1, o);
        ls2 += __shfl_xor_sync(0xffffffffu, ls2, o);
    }
    if (lane == 0) { wred[w4] = ls1; wred[4 + w4] = ls2; }
    __syncthreads();
    if (t == 0) {
        g_part_high[(b * 32 + tile) * 2 + 0] = wred[0] + wred[1] + wred[2] + wred[3];
        g_part_high[(b * 32 + tile) * 2 + 1] = wred[4] + wred[5] + wred[6] + wred[7];
    }
}

// ---------------- K3: u = conv1x1(low, Wlow) (24 -> 16), + GN-low partials
__global__ __launch_bounds__(256) void k3_low(
    const float* __restrict__ low, const float* __restrict__ Wlow) {
    __shared__ float sw[384];
    __shared__ float red[256];
    int t = threadIdx.x;
    int b = blockIdx.y;
    int p0 = blockIdx.x * 1024;
    for (int i = t; i < 384; i += 256) sw[i] = Wlow[i];
    __syncthreads();
    const float* lb = low + (size_t)b * 24 * HW + p0 + t;
    float* ub = g_u + (size_t)b * 16 * HW + p0 + t;
    float acc[4][16];
#pragma unroll
    for (int i = 0; i < 4; i++)
#pragma unroll
        for (int o = 0; o < 16; o++) acc[i][o] = 0.f;
    for (int c = 0; c < 24; c++) {
        float x0 = lb[c * HW], x1 = lb[c * HW + 256];
        float x2 = lb[c * HW + 512], x3 = lb[c * HW + 768];
#pragma unroll
        for (int o = 0; o < 16; o++) {
            float w = sw[o * 24 + c];
            acc[0][o] += x0 * w; acc[1][o] += x1 * w;
            acc[2][o] += x2 * w; acc[3][o] += x3 * w;
        }
    }
    float sv[4] = {0.f, 0.f, 0.f, 0.f};
#pragma unroll
    for (int o = 0; o < 16; o++) {
        float v0 = acc[0][o], v1 = acc[1][o], v2 = acc[2][o], v3 = acc[3][o];
        ub[o * HW] = v0; ub[o * HW + 256] = v1;
        ub[o * HW + 512] = v2; ub[o * HW + 768] = v3;
        int g = (o >> 3) * 2;
        sv[g] += v0 + v1 + v2 + v3;
        sv[g + 1] += v0 * v0 + v1 * v1 + v2 * v2 + v3 * v3;
    }
#pragma unroll
    for (int j = 0; j < 4; j++) {
        red[t] = sv[j]; __syncthreads();
        for (int s = 128; s > 0; s >>= 1) { if (t < s) red[t] += red[t + s]; __syncthreads(); }
        if (t == 0) g_part_low[(b * 16 + blockIdx.x) * 4 + j] = red[0];
        __syncthreads();
    }
}

// ---------------- K4: finalize stats for GN-high (1 group) and GN-low (2 groups)
__global__ void k4_stats1() {
    int b = blockIdx.x; int t = threadIdx.x; // 32 threads
    float h1 = g_part_high[(b * 32 + t) * 2 + 0];
    float h2 = g_part_high[(b * 32 + t) * 2 + 1];
    for (int o = 16; o; o >>= 1) {
        h1 += __shfl_xor_sync(0xffffffffu, h1, o);
        h2 += __shfl_xor_sync(0xffffffffu, h2, o);
    }
    float l[4];
#pragma unroll
    for (int j = 0; j < 4; j++) {
        float v = (t < 16) ? g_part_low[(b * 16 + t) * 4 + j] : 0.f;
        for (int o = 16; o; o >>= 1) v += __shfl_xor_sync(0xffffffffu, v, o);
        l[j] = v;
    }
    if (t == 0) {
        float nH = 16.f * HW;
        float mH = h1 / nH;
        g_stats1[b * 6 + 0] = mH;
        g_stats1[b * 6 + 1] = rsqrtf(h2 / nH - mH * mH + 1e-5f);
        float nL = 8.f * HW;
        float m0 = l[0] / nL;
        g_stats1[b * 6 + 2] = m0;
        g_stats1[b * 6 + 3] = rsqrtf(l[1] / nL - m0 * m0 + 1e-5f);
        float m1 = l[2] / nL;
        g_stats1[b * 6 + 4] = m1;
        g_stats1[b * 6 + 5] = rsqrtf(l[3] / nL - m1 * m1 + 1e-5f);
    }
}

// ---------------- K5: r = mish(GN(v)+GN(u)); z = conv3x3(r, Wref) via tf32 mma
// tile 32x16, 128 threads. M=16, K=144 (18 chunks), N=512.
__global__ __launch_bounds__(128) void k5_ref(
    const float* __restrict__ Wref,
    const float* __restrict__ gbn, const float* __restrict__ bbn,
    const float* __restrict__ glow, const float* __restrict__ blow) {
    __shared__ float sr[9792];       // [16][18][34], tf32-rounded mish values
    __shared__ float sw5[16 * 145];  // weights tf32, pitch 145
    __shared__ float sa1[16], sa2[16], sa3[16];
    __shared__ float wred[16];
    int t = threadIdx.x;
    int b = blockIdx.y;
    int tile = blockIdx.x;
    int x0 = (tile & 3) * 32, y0 = (tile >> 2) * 16;
    for (int i = t; i < 16 * 145; i += 128) {
        int o = i / 145, j = i - o * 145;
        sw5[i] = (j < 144) ? tf32r(Wref[o * 144 + j]) : 0.f;
    }
    if (t < 16) {
        int c = t, g = c >> 3;
        float mH = g_stats1[b * 6 + 0], rH = g_stats1[b * 6 + 1];
        float mL = g_stats1[b * 6 + 2 + 2 * g], rL = g_stats1[b * 6 + 3 + 2 * g];
        float a1 = rH * gbn[c], a2 = rL * glow[c];
        sa1[c] = a1; sa2[c] = a2;
        sa3[c] = bbn[c] + blow[c] - mH * a1 - mL * a2;
    }
    __syncthreads();
    const float* vb = g_v + (size_t)b * 16 * HW;
    const float* ub = g_u + (size_t)b * 16 * HW;
    for (int i = t; i < 9792; i += 128) {
        int c = i / 612; int rem = i - c * 612;
        int yy = rem / 34; int xx = rem - yy * 34;
        int gy = y0 - 1 + yy, gx = x0 - 1 + xx;
        float val = 0.f;
        if ((unsigned)gy < 128u && (unsigned)gx < 128u) {
            int off = c * HW + gy * WW + gx;
            val = mish_f(vb[off] * sa1[c] + ub[off] * sa2[c] + sa3[c]);
        }
        sr[i] = tf32r(val);
    }
    __syncthreads();
    int lane = t & 31, w4 = t >> 5;
    int grp = lane >> 2, qid = lane & 3;
    float acc[16][4];
#pragma unroll
    for (int g = 0; g < 16; g++) {
        acc[g][0] = 0.f; acc[g][1] = 0.f; acc[g][2] = 0.f; acc[g][3] = 0.f;
    }
    int pixB = (w4 * 4 * 34 + grp) * 4;
#pragma unroll 1
    for (int c = 0; c < 18; c++) {
        int k0 = c * 8 + qid;
        int ci0 = k0 / 9, r0 = k0 - ci0 * 9, ky0 = r0 / 3, kx0 = r0 - ky0 * 3;
        int k1 = k0 + 4;
        int ci1 = k1 / 9, r1 = k1 - ci1 * 9, ky1 = r1 / 3, kx1 = r1 - ky1 * 3;
        const float* p0 = (const float*)((const char*)sr + pixB + (ci0 * 612 + ky0 * 34 + kx0) * 4);
        const float* p1 = (const float*)((const char*)sr + pixB + (ci1 * 612 + ky1 * 34 + kx1) * 4);
        float a0 = sw5[grp * 145 + k0];
        float a1 = sw5[(grp + 8) * 145 + k0];
        float a2 = sw5[grp * 145 + k1];
        float a3 = sw5[(grp + 8) * 145 + k1];
#pragma unroll
        for (int g = 0; g < 16; g++) {
            int imm = (g >> 2) * 34 + (g & 3) * 8;
            mma8(acc[g][0], acc[g][1], acc[g][2], acc[g][3],
                 a0, a1, a2, a3, p0[imm], p1[imm]);
        }
    }
    float* zb = g_z + (size_t)b * 16 * HW;
    float sv[4] = {0.f, 0.f, 0.f, 0.f};
#pragma unroll
    for (int g = 0; g < 16; g++) {
        int gy = y0 + w4 * 4 + (g >> 2);
        int gx = x0 + (g & 3) * 8 + 2 * qid;
        float d0 = acc[g][0], d1 = acc[g][1], d2 = acc[g][2], d3 = acc[g][3];
        float2 s0; s0.x = d0; s0.y = d1;
        float2 s1; s1.x = d2; s1.y = d3;
        *(float2*)&zb[grp * HW + gy * WW + gx] = s0;          // channels 0..7
        *(float2*)&zb[(grp + 8) * HW + gy * WW + gx] = s1;    // channels 8..15
        sv[0] += d0 + d1; sv[1] += d0 * d0 + d1 * d1;
        sv[2] += d2 + d3; sv[3] += d2 * d2 + d3 * d3;
    }
#pragma unroll
    for (int o = 16; o; o >>= 1) {
#pragma unroll
        for (int j = 0; j < 4; j++) sv[j] += __shfl_xor_sync(0xffffffffu, sv[j], o);
    }
    if (lane == 0) {
#pragma unroll
        for (int j = 0; j < 4; j++) wred[w4 * 4 + j] = sv[j];
    }
    __syncthreads();
    if (t == 0) {
#pragma unroll
        for (int j = 0; j < 4; j++)
            g_part_z[(b * 32 + tile) * 4 + j] =
                wred[j] + wred[4 + j] + wred[8 + j] + wred[12 + j];
    }
}

// ---------------- K6: finalize GN-z stats (2 groups)
__global__ void k6_stats2() {
    int b = blockIdx.x; int t = threadIdx.x; // 32 threads
    float l[4];
#pragma unroll
    for (int j = 0; j < 4; j++) {
        float v = g_part_z[(b * 32 + t) * 4 + j];
        for (int o = 16; o; o >>= 1) v += __shfl_xor_sync(0xffffffffu, v, o);
        l[j] = v;
    }
    if (t == 0) {
        float n = 8.f * HW;
        float m0 = l[0] / n;
        g_stats2[b * 4 + 0] = m0;
        g_stats2[b * 4 + 1] = rsqrtf(l[1] / n - m0 * m0 + 1e-5f);
        float m1 = l[2] / n;
        g_stats2[b * 4 + 2] = m1;
        g_stats2[b * 4 + 3] = rsqrtf(l[3] / n - m1 * m1 + 1e-5f);
    }
}

// ---------------- K7: seg = conv1x1(mish(GN(z)), Wseg)
__global__ __launch_bounds__(256) void k7_seg(
    const float* __restrict__ gref, const float* __restrict__ bref,
    const float* __restrict__ Wseg) {
    __shared__ float sa[16], sb[16], sws[16];
    int t = threadIdx.x, b = blockIdx.y;
    int p = blockIdx.x * 256 + t;
    if (t < 16) {
        int g = t >> 3;
        float m = g_stats2[b * 4 + 2 * g], r = g_stats2[b * 4 + 1 + 2 * g];
        float a = r * gref[t];
        sa[t] = a; sb[t] = bref[t] - m * a; sws[t] = Wseg[t];
    }
    __syncthreads();
    const float* zb = g_z + (size_t)b * 16 * HW + p;
    float acc = 0.f;
#pragma unroll
    for (int c = 0; c < 16; c++) {
        float zn = zb[c * HW] * sa[c] + sb[c];
        acc += mish_f(zn) * sws[c];
    }
    g_seg[b * HW + p] = acc;
}

// ---------------- K8: bilinear 128->512 (half-pixel centers, clamp) + sigmoid
__global__ __launch_bounds__(256) void k8_up(float4* __restrict__ out) {
    int idx4 = blockIdx.x * 256 + threadIdx.x;
    int idx = idx4 * 4;
    int b = idx >> 18;
    int rem = idx & 262143;
    int oy = rem >> 9, ox0 = rem & 511;
    float sy = (oy + 0.5f) * 0.25f - 0.5f;
    sy = fminf(fmaxf(sy, 0.f), 127.f);
    int y0 = (int)sy;
    float fy = sy - y0;
    int y1 = min(y0 + 1, 127);
    const float* s = g_seg + b * HW;
    const float* r0 = s + y0 * 128;
    const float* r1 = s + y1 * 128;
    float4 o4;
    float res[4];
#pragma unroll
    for (int j = 0; j < 4; j++) {
        int ox = ox0 + j;
        float sx = (ox + 0.5f) * 0.25f - 0.5f;
        sx = fminf(fmaxf(sx, 0.f), 127.f);
        int x0 = (int)sx;
        float fx = sx - x0;
        int x1 = min(x0 + 1, 127);
        float top = r0[x0] + (r0[x1] - r0[x0]) * fx;
        float bot = r1[x0] + (r1[x1] - r1[x0]) * fx;
        float v = top + (bot - top) * fy;
        res[j] = 1.f / (1.f + __expf(-v));
    }
    o4.x = res[0]; o4.y = res[1]; o4.z = res[2]; o4.w = res[3];
    out[idx4] = o4;
}

// ---------------- launch ----------------
extern "C" void kernel_launch(void* const* d_in, const int* in_sizes, int n_in,
                              void* d_out, int out_size) {
    (void)in_sizes; (void)n_in; (void)out_size;
    const float* low  = (const float*)d_in[0];
    const float* high = (const float*)d_in[1];
    const float* Wc0  = (const float*)d_in[2];
    const float* Wc1  = (const float*)d_in[3];
    const float* Wc2  = (const float*)d_in[4];
    const float* gbn  = (const float*)d_in[5];
    const float* bbn  = (const float*)d_in[6];
    const float* Wlow = (const float*)d_in[7];
    const float* glow = (const float*)d_in[8];
    const float* blow = (const float*)d_in[9];
    const float* Wref = (const float*)d_in[10];
    const float* gref = (const float*)d_in[11];
    const float* bref = (const float*)d_in[12];
    const float* Wseg = (const float*)d_in[13];
    float* out = (float*)d_out;

    k1_conv1x1_high<<<dim3(16, 48), 256>>>(high, Wc0);
    k2_branch<<<dim3(32, 48), 128>>>(Wc1, Wc2);
    k3_low<<<dim3(16, 48), 256>>>(low, Wlow);
    k4_stats1<<<48, 32>>>();
    k5_ref<<<dim3(32, 48), 128>>>(Wref, gbn, bbn, glow, blow);
    k6_stats2<<<48, 32>>>();
    k7_seg<<<dim3(64, 48), 256>>>(gref, bref, Wseg);
    k8_up<<<12288, 256>>>((float4*)out);
}